// round 17
// baseline (speedup 1.0000x reference)
#include <cuda_runtime.h>
#include <cuda_bf16.h>
#include <cstdint>

// LocalVariation: x [16,1,512,512] f32 -> out [16,24,512,512] f32
// out[b, k(i,j), y, x] = x[b,y,x] - x[b, clamp(y+i-2), clamp(x+j-2)]
// for (i,j) in 5x5 window excluding center, replicate padding.
//
// DRAM-write-bound (~403 MB). This variant removes the per-lane STG path
// entirely: each CTA (128 threads) computes one full 512-px row for all 24
// channels into 48 KB of SMEM, then each warp's elected lane issues 6
// contiguous 2 KB cp.async.bulk (TMA) stores (24 total). Stores become
// clean linear bursts driven by the TMA engine, decoupled from warp issue
// and the L1 STG wavefront path pinned at ~64% in every STG-based variant.

#define LV_H 512
#define LV_W 512
#define LV_B 16
#define LV_NCH 24
#define LV_HW (LV_H * LV_W)
#define ROW_BYTES (LV_W * 4)   // 2048

__global__ __launch_bounds__(128)
void localvariation_kernel(const float* __restrict__ x, float* __restrict__ out)
{
    __shared__ float srow[LV_NCH * LV_W];   // 48 KB

    const int tx = threadIdx.x;             // 0..127
    const int x0 = tx * 4;                  // base x of 4-pixel group
    const int y  = blockIdx.x;              // 0..511
    const int b  = blockIdx.y;              // 0..15

    const float* __restrict__ xb = x + (size_t)b * LV_HW;

    // Center values: aligned float4 at (y, x0) — never needs clamping.
    const float4 cc = *reinterpret_cast<const float4*>(xb + (size_t)y * LV_W + x0);
    const float c0 = cc.x, c1 = cc.y, c2 = cc.z, c3 = cc.w;

    int k = 0;
#pragma unroll
    for (int i = 0; i < 5; i++) {
        int yy = y + i - 2;
        yy = yy < 0 ? 0 : (yy > LV_H - 1 ? LV_H - 1 : yy);
        const float* __restrict__ row = xb + (size_t)yy * LV_W;

        // 8-wide clamped row segment [x0-2, x0+5].
        float r[8];
#pragma unroll
        for (int j = 0; j < 8; j++) {
            int xx = x0 + j - 2;
            xx = xx < 0 ? 0 : (xx > LV_W - 1 ? LV_W - 1 : xx);
            r[j] = __ldg(row + xx);
        }

#pragma unroll
        for (int j = 0; j < 5; j++) {
            if (i == 2 && j == 2) continue;
            float4 v;
            v.x = c0 - r[j + 0];
            v.y = c1 - r[j + 1];
            v.z = c2 - r[j + 2];
            v.w = c3 - r[j + 3];
            *reinterpret_cast<float4*>(&srow[k * LV_W + x0]) = v;
            k++;
        }
    }

    __syncthreads();
    // Order generic-proxy SMEM writes before async-proxy (TMA) reads.
    asm volatile("fence.proxy.async.shared::cta;" ::: "memory");

    // Each warp's lane 0 issues 6 channel copies: warp w -> channels 6w..6w+5.
    const int wid = tx >> 5;
    const int lid = tx & 31;
    if (lid == 0) {
        uint32_t sbase;
        asm("{ .reg .u64 t; cvta.to.shared.u64 t, %1; cvt.u32.u64 %0, t; }"
            : "=r"(sbase) : "l"((const void*)srow));

        float* __restrict__ obase = out + (size_t)b * LV_NCH * LV_HW
                                        + (size_t)y * LV_W;
#pragma unroll
        for (int c = 0; c < 6; c++) {
            const int ch = wid * 6 + c;
            const float* gdst = obase + (size_t)ch * LV_HW;
            asm volatile(
                "cp.async.bulk.global.shared::cta.bulk_group [%0], [%1], %2;"
                :: "l"(gdst), "r"(sbase + ch * ROW_BYTES), "r"(ROW_BYTES)
                : "memory");
        }
        asm volatile("cp.async.bulk.commit_group;" ::: "memory");
        // CTA may not release SMEM until the bulk copies finish reading it.
        asm volatile("cp.async.bulk.wait_group.read 0;" ::: "memory");
    }
}

extern "C" void kernel_launch(void* const* d_in, const int* in_sizes, int n_in,
                              void* d_out, int out_size)
{
    const float* x = (const float*)d_in[0];
    float* out = (float*)d_out;

    dim3 block(128, 1, 1);                 // one warpgroup: one full image row
    dim3 grid(LV_H, LV_B, 1);              // (512, 16) = 8192 blocks
    localvariation_kernel<<<grid, block>>>(x, out);
}